// round 17
// baseline (speedup 1.0000x reference)
#include <cuda_runtime.h>
#include <cuda_bf16.h>

// AMSoftmaxLoss: score (2048 x 50257) fp32, labels (2048) int32 in {0,1}
// Hybrid LPT grid: 1184 full-row blocks (exactly wave 1, max per-active
// efficiency) + 864 rows x 4 quarter-row blocks (fine-grained tail fill).
// One unified 4-deep LDG.128 loop; fused last-arriving-block finale.

#define NROWS 2048
#define CCOLS 50257
#define BLK   256
#define NFULL 1184                 // rows 0..1183: one block per row
#define NQR   (NROWS - NFULL)      // 864 rows split in quarters
#define QW    12565                // 3*12565 + 12562 = 50257
#define NBLKS (NFULL + NQR * 4)    // 4640

__device__ float g_part[NBLKS];
__device__ unsigned int g_count = 0;   // self-resetting via atomicInc wrap

__device__ __forceinline__ float ex2f(float x) {
    float y;
    asm("ex2.approx.ftz.f32 %0, %1;" : "=f"(y) : "f"(x));
    return y;
}

#define SL2E (30.0f * 1.44269504088896340736f)   // S * log2(e)

__global__ __launch_bounds__(BLK) void amsm_kernel(
    const float* __restrict__ score,
    const int* __restrict__ labels,
    float* __restrict__ out)
{
    const int b    = blockIdx.x;
    const int tid  = threadIdx.x;
    const int lane = tid & 31;
    const int wid  = tid >> 5;

    // bid -> (row, col0, len): fulls first (wave 1), then quarters.
    int row, col0, len;
    if (b < NFULL) {
        row = b; col0 = 0; len = CCOLS;
    } else {
        int t = b - NFULL;
        row  = NFULL + (t >> 2);
        int s = t & 3;
        col0 = s * QW;
        len  = (s == 3) ? (CCOLS - 3 * QW) : QW;
    }

    const float* __restrict__ p = score + (size_t)row * CCOLS + col0;

    float s0 = 0.f, s1 = 0.f, s2 = 0.f, s3 = 0.f;

    int peel = (-(row * CCOLS + col0)) & 3;        // to 16B alignment
    if (tid < peel) s0 += ex2f(SL2E * p[tid]);

    const int n4 = (len - peel) >> 2;
    const float4* __restrict__ q = (const float4*)(p + peel);

    int i = tid;
    for (; i + 3 * BLK < n4; i += 4 * BLK) {       // 4 LDG.128 in flight
        float4 a = q[i];
        float4 bb = q[i + BLK];
        float4 c = q[i + 2 * BLK];
        float4 d = q[i + 3 * BLK];
        s0 += ex2f(SL2E * a.x);  s1 += ex2f(SL2E * a.y);
        s2 += ex2f(SL2E * a.z);  s3 += ex2f(SL2E * a.w);
        s0 += ex2f(SL2E * bb.x); s1 += ex2f(SL2E * bb.y);
        s2 += ex2f(SL2E * bb.z); s3 += ex2f(SL2E * bb.w);
        s0 += ex2f(SL2E * c.x);  s1 += ex2f(SL2E * c.y);
        s2 += ex2f(SL2E * c.z);  s3 += ex2f(SL2E * c.w);
        s0 += ex2f(SL2E * d.x);  s1 += ex2f(SL2E * d.y);
        s2 += ex2f(SL2E * d.z);  s3 += ex2f(SL2E * d.w);
    }
    for (; i < n4; i += BLK) {
        float4 a = q[i];
        s0 += ex2f(SL2E * a.x); s1 += ex2f(SL2E * a.y);
        s2 += ex2f(SL2E * a.z); s3 += ex2f(SL2E * a.w);
    }
    const int done = peel + 4 * n4;
    if (tid < len - done) s0 += ex2f(SL2E * p[done + tid]);

    float v = (s0 + s1) + (s2 + s3);

    // Block reduction: warp shuffle then cross-warp via smem.
    __shared__ float wsum[BLK / 32];
    #pragma unroll
    for (int off = 16; off > 0; off >>= 1)
        v += __shfl_down_sync(0xFFFFFFFFu, v, off);
    if (lane == 0) wsum[wid] = v;
    __syncthreads();

    __shared__ unsigned s_last;
    if (tid == 0) {
        float w = 0.f;
        #pragma unroll
        for (int k = 0; k < BLK / 32; k++) w += wsum[k];
        g_part[b] = w;
        __threadfence();
        unsigned old = atomicInc(&g_count, NBLKS - 1);   // wraps -> self-reset
        s_last = (old == NBLKS - 1) ? 1u : 0u;
    }
    __syncthreads();
    if (!s_last) return;

    // ---- Last-arriving block: fold partials, per-row epilogue, mean ----
    volatile float* gp = g_part;
    double acc = 0.0;
    for (int r = tid; r < NROWS; r += BLK) {
        float rs;
        if (r < NFULL) {
            rs = gp[r];
        } else {
            int base = NFULL + (r - NFULL) * 4;
            rs = (gp[base] + gp[base + 1]) + (gp[base + 2] + gp[base + 3]);
        }

        int lab = labels[r] & 1;
        float m = lab ? 0.4f : 0.1f;
        float tg = __ldg(score + (size_t)r * CCOLS + lab);
        float num = 30.0f * (tg - m);
        float excl = rs - ex2f(SL2E * tg);
        float denom = ex2f(num * 1.44269504088896340736f) + excl;
        acc += (double)(num - logf(denom));
    }

    __shared__ double dred[BLK];
    dred[tid] = acc;
    __syncthreads();
    #pragma unroll
    for (int off = BLK / 2; off > 0; off >>= 1) {
        if (tid < off) dred[tid] += dred[tid + off];
        __syncthreads();
    }
    if (tid == 0)
        out[0] = (float)(-dred[0] / (double)NROWS);
}

extern "C" void kernel_launch(void* const* d_in, const int* in_sizes, int n_in,
                              void* d_out, int out_size)
{
    const float* score = (const float*)d_in[0];
    const int* labels = (const int*)d_in[1];
    float* out = (float*)d_out;

    amsm_kernel<<<NBLKS, BLK>>>(score, labels, out);
}